// round 1
// baseline (speedup 1.0000x reference)
#include <cuda_runtime.h>

// ---------------------------------------------------------------------------
// Problem constants
// ---------------------------------------------------------------------------
namespace {
constexpr int Bc   = 4;
constexpr int Cc   = 64;
constexpr int Hc   = 256;
constexpr int Wc   = 320;
constexpr int HWc  = Hc * Wc;        // 81920
constexpr int NPIX = Bc * HWc;       // 327680
constexpr int NB   = 1280;           // pixel-blocks per conv group (10 x 128)
constexpr int OCG  = 14;             // output channels per conv group
constexpr int NG   = 6;              // groups -> 84 padded channels (83 used)
}

// ---------------------------------------------------------------------------
// Device scratch (static allocations only -- no cudaMalloc allowed)
// ---------------------------------------------------------------------------
__device__ float g_wall[84 * 576];      // packed conv weights [oc][ic][tap]
__device__ float g_bias[84];            // bias (ck only, else 0)
__device__ float g_sp[83];              // spatial gaussian tables (9+25+49)
__device__ float g_conv[83 * NPIX];     // raw conv outputs [oc][pix]
__device__ float g_psum[80 * NB];       // BN partial sums
__device__ float g_psq[80 * NB];        // BN partial sum-squares
__device__ float g_bnscale[80];
__device__ float g_bnshift[80];
__device__ float g_weights[83 * NPIX];  // normalized per-pixel kernels [k][pix]
__device__ float g_conf[3 * NPIX];
__device__ float g_hn[6 * NPIX];        // ping-pong hn3/5/7
__device__ float g_hns[3 * NPIX];       // hn, mid blend, final blend

// ---------------------------------------------------------------------------
// f32x2 packed-FMA helpers (sm_100+: fma.rn.f32x2 -> FFMA2, 2x fp32 rate)
// ---------------------------------------------------------------------------
__device__ __forceinline__ unsigned long long pk2(float lo, float hi) {
    unsigned long long r;
    asm("mov.b64 %0,{%1,%2};" : "=l"(r) : "f"(lo), "f"(hi));
    return r;
}
__device__ __forceinline__ unsigned long long splat2(float v) { return pk2(v, v); }
__device__ __forceinline__ void fma2(unsigned long long& d, unsigned long long a,
                                     unsigned long long b) {
    asm("fma.rn.f32x2 %0,%1,%2,%3;" : "=l"(d) : "l"(a), "l"(b), "l"(d));
}
__device__ __forceinline__ void unpk2(unsigned long long v, float& lo, float& hi) {
    asm("mov.b64 {%0,%1},%2;" : "=f"(lo), "=f"(hi) : "l"(v));
}

// ---------------------------------------------------------------------------
// K0a: pack all conv weights into one padded [84][64][9] tensor + bias
// ---------------------------------------------------------------------------
__global__ void k_pack(const float* __restrict__ w3, const float* __restrict__ w5,
                       const float* __restrict__ w7, const float* __restrict__ ckw,
                       const float* __restrict__ ckb) {
    int i0 = blockIdx.x * blockDim.x + threadIdx.x;
    for (int idx = i0; idx < 84 * 576; idx += gridDim.x * blockDim.x) {
        int oc = idx / 576, rest = idx % 576;
        float v = 0.f;
        if (oc < 8)        v = w3[oc * 576 + rest];
        else if (oc < 32)  v = w5[(oc - 8) * 576 + rest];
        else if (oc < 80)  v = w7[(oc - 32) * 576 + rest];
        else if (oc < 83)  v = ckw[(oc - 80) * 576 + rest];
        g_wall[idx] = v;
    }
    if (i0 < 84) g_bias[i0] = (i0 >= 80 && i0 < 83) ? ckb[i0 - 80] : 0.f;
}

// ---------------------------------------------------------------------------
// K0b: spatial gaussian tables from device-resident sigmas
// ---------------------------------------------------------------------------
__global__ void k_sp(const float* __restrict__ s3, const float* __restrict__ s5,
                     const float* __restrict__ s7) {
    int t = threadIdx.x;
    if (t >= 83) return;
    int d, k;
    float sig;
    if (t < 9)       { d = 3; k = t;      sig = *s3; }
    else if (t < 34) { d = 5; k = t - 9;  sig = *s5; }
    else             { d = 7; k = t - 34; sig = *s7; }
    int kh = k / d, kw = k % d;
    float x = -1.f + 2.f * (float)kh / (float)(d - 1);
    float y = -1.f + 2.f * (float)kw / (float)(d - 1);
    g_sp[t] = expf(-(x * x + y * y) / (2.f * sig * sig));
}

// ---------------------------------------------------------------------------
// K1: 83-channel 3x3 conv over fout (smem-tiled, f32x2 packed accumulators)
//     grid (10, 128, 6): x = W tile, y = H tile * batch, z = oc group
//     Also emits deterministic per-block BN partial sums for channels 0..79.
// ---------------------------------------------------------------------------
__global__ __launch_bounds__(256) void k_conv(const float* __restrict__ fout) {
    __shared__ float  s_in[8][10][34];
    __shared__ float2 s_w[8][9][7];
    __shared__ float  s_rs[8][14];
    __shared__ float  s_rq[8][14];

    const int tx = threadIdx.x & 31;
    const int ty = threadIdx.x >> 5;
    const int b  = blockIdx.y >> 5;
    const int y0 = (blockIdx.y & 31) * 8;
    const int x0 = blockIdx.x * 32;
    const int ocb = blockIdx.z * OCG;

    unsigned long long acc[7] = {};

    for (int icb = 0; icb < Cc; icb += 8) {
        __syncthreads();
        // weights: 8 ic x 9 taps x 14 oc = 1008 floats
        for (int idx = threadIdx.x; idx < 1008; idx += 256) {
            int j = idx % 14, t = (idx / 14) % 9, ic = idx / 126;
            ((float*)s_w)[ic * 126 + t * 14 + j] =
                g_wall[(ocb + j) * 576 + (icb + ic) * 9 + t];
        }
        // input tile: 8 ic x 10 x 34 (zero-padded halo)
        for (int idx = threadIdx.x; idx < 2720; idx += 256) {
            int ic = idx / 340, rem = idx % 340;
            int r = rem / 34, c = rem % 34;
            int gh = y0 + r - 1, gw = x0 + c - 1;
            float v = 0.f;
            if ((unsigned)gh < (unsigned)Hc && (unsigned)gw < (unsigned)Wc)
                v = fout[((b * Cc + icb + ic) * Hc + gh) * Wc + gw];
            s_in[ic][r][c] = v;
        }
        __syncthreads();
#pragma unroll
        for (int ic = 0; ic < 8; ic++) {
            float v[9];
#pragma unroll
            for (int t = 0; t < 9; t++) v[t] = s_in[ic][ty + t / 3][tx + t % 3];
#pragma unroll
            for (int t = 0; t < 9; t++) {
                unsigned long long vv = splat2(v[t]);
#pragma unroll
                for (int p = 0; p < 7; p++) {
                    unsigned long long w2 =
                        *(const unsigned long long*)&s_w[ic][t][p];
                    fma2(acc[p], vv, w2);
                }
            }
        }
    }

    const int pix = b * HWc + (y0 + ty) * Wc + (x0 + tx);
    float fv[14];
#pragma unroll
    for (int p = 0; p < 7; p++) unpk2(acc[p], fv[2 * p], fv[2 * p + 1]);
#pragma unroll
    for (int j = 0; j < 14; j++) {
        int oc = ocb + j;
        if (oc < 83) g_conv[oc * NPIX + pix] = fv[j] + g_bias[oc];
    }

    // BN partial sums (pre-bias conv values; bias is zero on these channels)
#pragma unroll
    for (int j = 0; j < 14; j++) {
        float s = fv[j], q = fv[j] * fv[j];
#pragma unroll
        for (int off = 16; off; off >>= 1) {
            s += __shfl_xor_sync(0xffffffffu, s, off);
            q += __shfl_xor_sync(0xffffffffu, q, off);
        }
        if (tx == 0) { s_rs[ty][j] = s; s_rq[ty][j] = q; }
    }
    __syncthreads();
    if (threadIdx.x < 14) {
        int oc = ocb + threadIdx.x;
        if (oc < 80) {
            float S = 0.f, Q = 0.f;
#pragma unroll
            for (int w8 = 0; w8 < 8; w8++) { S += s_rs[w8][threadIdx.x]; Q += s_rq[w8][threadIdx.x]; }
            int pb = blockIdx.x + 10 * blockIdx.y;
            g_psum[oc * NB + pb] = S;
            g_psq[oc * NB + pb]  = Q;
        }
    }
}

// ---------------------------------------------------------------------------
// K2: finalize batchnorm statistics -> per-channel scale/shift
// ---------------------------------------------------------------------------
__global__ void k_bnstats(const float* __restrict__ g3, const float* __restrict__ b3,
                          const float* __restrict__ g5, const float* __restrict__ b5,
                          const float* __restrict__ g7, const float* __restrict__ b7) {
    __shared__ float sh[256], shq[256];
    int c = blockIdx.x;
    float S = 0.f, Q = 0.f;
    for (int i = threadIdx.x; i < NB; i += 256) {
        S += g_psum[c * NB + i];
        Q += g_psq[c * NB + i];
    }
    sh[threadIdx.x] = S; shq[threadIdx.x] = Q;
    __syncthreads();
    for (int s = 128; s; s >>= 1) {
        if (threadIdx.x < s) { sh[threadIdx.x] += sh[threadIdx.x + s]; shq[threadIdx.x] += shq[threadIdx.x + s]; }
        __syncthreads();
    }
    if (threadIdx.x == 0) {
        float mean = sh[0] / (float)NPIX;
        float var  = shq[0] / (float)NPIX - mean * mean;
        float gg, bb;
        if (c < 8)       { gg = g3[c];      bb = b3[c]; }
        else if (c < 32) { gg = g5[c - 8];  bb = b5[c - 8]; }
        else             { gg = g7[c - 32]; bb = b7[c - 32]; }
        float sc = gg / sqrtf(var + 1e-5f);
        g_bnscale[c] = sc;
        g_bnshift[c] = bb - mean * sc;
    }
}

// ---------------------------------------------------------------------------
// K3: per-pixel kernel generation + conf softmax + hn init
// ---------------------------------------------------------------------------
template <int N, int HF>
__device__ __forceinline__ void gen_group(int pix, int ocb, int spo) {
    float wv[N];
    float s = 0.f;
#pragma unroll
    for (int i = 0; i < N; i++) {
        float v = g_conv[(ocb + i) * NPIX + pix];
        v = fmaxf(fmaf(v, g_bnscale[ocb + i], g_bnshift[ocb + i]), 0.f);
        wv[i] = v;
        s += v;
    }
    float inv = 1.f / (s + 1e-6f);
    float mid = 1e-6f * inv;                // == 1 - s/(s+eps)
    float tot = mid * g_sp[spo + HF];
#pragma unroll
    for (int i = 0; i < N; i++) {
        int k = (i < HF) ? i : i + 1;
        tot += wv[i] * inv * g_sp[spo + k];
    }
    float sc = 1.f / fmaxf(tot, 1e-7f);
    g_weights[(spo + HF) * NPIX + pix] = mid * g_sp[spo + HF] * sc;
#pragma unroll
    for (int i = 0; i < N; i++) {
        int k = (i < HF) ? i : i + 1;
        g_weights[(spo + k) * NPIX + pix] = wv[i] * inv * g_sp[spo + k] * sc;
    }
}

__global__ __launch_bounds__(256) void k_wgen(const float* __restrict__ hn) {
    int pix = blockIdx.x * 256 + threadIdx.x;
    gen_group<8, 4>(pix, 0, 0);
    gen_group<24, 12>(pix, 8, 9);
    gen_group<48, 24>(pix, 32, 34);
    float c0 = g_conv[80 * NPIX + pix];
    float c1 = g_conv[81 * NPIX + pix];
    float c2 = g_conv[82 * NPIX + pix];
    float m = fmaxf(c0, fmaxf(c1, c2));
    float e0 = expf(c0 - m), e1 = expf(c1 - m), e2 = expf(c2 - m);
    float inv = 1.f / (e0 + e1 + e2);
    g_conf[pix]            = e0 * inv;
    g_conf[NPIX + pix]     = e1 * inv;
    g_conf[2 * NPIX + pix] = e2 * inv;
    float h = hn[pix];
    g_hn[pix] = h; g_hn[NPIX + pix] = h; g_hn[2 * NPIX + pix] = h;
    g_hns[pix] = h;
}

// ---------------------------------------------------------------------------
// K4: one propagation step for all three kernel sizes (ping-pong buffers)
// ---------------------------------------------------------------------------
template <int PK, int R, int SPO>
__device__ __forceinline__ float prop_one(int pix, int h, int w,
                                          const float* __restrict__ hsrc) {
    float o = 0.f;
#pragma unroll
    for (int kh = 0; kh < PK; kh++) {
        int hh = h + kh - R;
#pragma unroll
        for (int kw = 0; kw < PK; kw++) {
            int ww = w + kw - R;
            float x = 0.f;
            if ((unsigned)hh < (unsigned)Hc && (unsigned)ww < (unsigned)Wc)
                x = hsrc[pix + (kh - R) * Wc + (kw - R)];
            o = fmaf(g_weights[(SPO + kh * PK + kw) * NPIX + pix], x, o);
        }
    }
    return o;
}

__global__ __launch_bounds__(256) void k_prop(int srcBase, int dstBase, int blendIdx) {
    int pix = blockIdx.x * 256 + threadIdx.x;
    int rp = pix % HWc;
    int h = rp / Wc, w = rp % Wc;
    float o3 = prop_one<3, 1, 0>(pix, h, w, g_hn + (srcBase + 0) * NPIX);
    float o5 = prop_one<5, 2, 9>(pix, h, w, g_hn + (srcBase + 1) * NPIX);
    float o7 = prop_one<7, 3, 34>(pix, h, w, g_hn + (srcBase + 2) * NPIX);
    g_hn[(dstBase + 0) * NPIX + pix] = o3;
    g_hn[(dstBase + 1) * NPIX + pix] = o5;
    g_hn[(dstBase + 2) * NPIX + pix] = o7;
    if (blendIdx >= 0) {
        float r = g_conf[pix] * o3 + g_conf[NPIX + pix] * o5 + g_conf[2 * NPIX + pix] * o7;
        g_hns[blendIdx * NPIX + pix] = r;
    }
}

// ---------------------------------------------------------------------------
// K5: final 67->3 conv + softmax + weighted blend -> output
//     tile 64x16 px, 128 threads, each thread an 8-px strip, f32x2 FMAs
// ---------------------------------------------------------------------------
__global__ __launch_bounds__(128) void k_final(const float* __restrict__ fout,
                                               const float* __restrict__ ctw,
                                               const float* __restrict__ ctb,
                                               float* __restrict__ out) {
    __shared__ float s_t[2][18][66];
    __shared__ float s_wt[67][9][3];

    const int tid = threadIdx.x;
    const int sx = tid & 7, yy = tid >> 3;          // strip 0..7, row 0..15
    const int b = blockIdx.z;
    const int x0 = blockIdx.x * 64, y0 = blockIdx.y * 16;

    for (int idx = tid; idx < 67 * 27; idx += 128) {
        int o = idx % 3, t = (idx / 3) % 9, i = idx / 27;
        s_wt[i][t][o] = ctw[(o * 67 + i) * 9 + t];
    }

    unsigned long long acc[3][4] = {};

    for (int ic0 = 0; ic0 < 67; ic0 += 2) {
        int nic = (67 - ic0) < 2 ? (67 - ic0) : 2;
        __syncthreads();
        for (int idx = tid; idx < nic * 1188; idx += 128) {
            int icl = idx / 1188, rem = idx % 1188;
            int r = rem / 66, c = rem % 66;
            int gh = y0 + r - 1, gw = x0 + c - 1;
            float v = 0.f;
            if ((unsigned)gh < (unsigned)Hc && (unsigned)gw < (unsigned)Wc) {
                int ic = ic0 + icl;
                v = (ic < 64) ? fout[((b * Cc + ic) * Hc + gh) * Wc + gw]
                              : g_hns[(ic - 64) * NPIX + b * HWc + gh * Wc + gw];
            }
            s_t[icl][r][c] = v;
        }
        __syncthreads();
        for (int icl = 0; icl < nic; icl++) {
            const int ic = ic0 + icl;
            const int c0 = sx * 8;
            float r0[10], r1[10], r2[10];
#pragma unroll
            for (int c = 0; c < 10; c++) {
                r0[c] = s_t[icl][yy][c0 + c];
                r1[c] = s_t[icl][yy + 1][c0 + c];
                r2[c] = s_t[icl][yy + 2][c0 + c];
            }
            unsigned long long p0[9], p1[9], p2[9];
#pragma unroll
            for (int c = 0; c < 9; c++) {
                p0[c] = pk2(r0[c], r0[c + 1]);
                p1[c] = pk2(r1[c], r1[c + 1]);
                p2[c] = pk2(r2[c], r2[c + 1]);
            }
#pragma unroll
            for (int kh = 0; kh < 3; kh++) {
                const unsigned long long* pr = (kh == 0) ? p0 : (kh == 1) ? p1 : p2;
#pragma unroll
                for (int kw = 0; kw < 3; kw++) {
#pragma unroll
                    for (int o = 0; o < 3; o++) {
                        unsigned long long ws = splat2(s_wt[ic][kh * 3 + kw][o]);
#pragma unroll
                        for (int j = 0; j < 4; j++) fma2(acc[o][j], pr[kw + 2 * j], ws);
                    }
                }
            }
        }
    }

    float a[3][8];
#pragma unroll
    for (int o = 0; o < 3; o++)
#pragma unroll
        for (int j = 0; j < 4; j++) unpk2(acc[o][j], a[o][2 * j], a[o][2 * j + 1]);

    float bb0 = ctb[0], bb1 = ctb[1], bb2 = ctb[2];
    int basepix = b * HWc + (y0 + yy) * Wc + x0 + sx * 8;
#pragma unroll
    for (int e = 0; e < 8; e++) {
        float v0 = a[0][e] + bb0, v1 = a[1][e] + bb1, v2 = a[2][e] + bb2;
        float m = fmaxf(v0, fmaxf(v1, v2));
        float e0 = expf(v0 - m), e1 = expf(v1 - m), e2 = expf(v2 - m);
        float inv = 1.f / (e0 + e1 + e2);
        int pix = basepix + e;
        float h0v = g_hns[pix], h1v = g_hns[NPIX + pix], h2v = g_hns[2 * NPIX + pix];
        out[pix] = (e0 * h0v + e1 * h1v + e2 * h2v) * inv;
    }
}

// ---------------------------------------------------------------------------
// Launcher
// ---------------------------------------------------------------------------
extern "C" void kernel_launch(void* const* d_in, const int* in_sizes, int n_in,
                              void* d_out, int out_size) {
    const float* fout = (const float*)d_in[0];
    const float* hn   = (const float*)d_in[1];
    // d_in[2] = h0 (unused by reference)
    const float* w3c  = (const float*)d_in[3];
    const float* w3g  = (const float*)d_in[4];
    const float* w3b  = (const float*)d_in[5];
    const float* w5c  = (const float*)d_in[6];
    const float* w5g  = (const float*)d_in[7];
    const float* w5b  = (const float*)d_in[8];
    const float* w7c  = (const float*)d_in[9];
    const float* w7g  = (const float*)d_in[10];
    const float* w7b  = (const float*)d_in[11];
    const float* ckw  = (const float*)d_in[12];
    const float* ckb  = (const float*)d_in[13];
    const float* ctw  = (const float*)d_in[14];
    const float* ctb  = (const float*)d_in[15];
    const float* sig3 = (const float*)d_in[16];
    const float* sig5 = (const float*)d_in[17];
    const float* sig7 = (const float*)d_in[18];
    float* out = (float*)d_out;

    k_pack<<<64, 256>>>(w3c, w5c, w7c, ckw, ckb);
    k_sp<<<1, 128>>>(sig3, sig5, sig7);
    k_conv<<<dim3(10, 128, NG), 256>>>(fout);
    k_bnstats<<<80, 256>>>(w3g, w3b, w5g, w5b, w7g, w7b);
    k_wgen<<<NPIX / 256, 256>>>(hn);
    k_prop<<<NPIX / 256, 256>>>(0, 3, -1);
    k_prop<<<NPIX / 256, 256>>>(3, 0, -1);
    k_prop<<<NPIX / 256, 256>>>(0, 3, 1);   // i == PT/2-1 -> hns[1]
    k_prop<<<NPIX / 256, 256>>>(3, 0, -1);
    k_prop<<<NPIX / 256, 256>>>(0, 3, -1);
    k_prop<<<NPIX / 256, 256>>>(3, 0, 2);   // final -> hns[2]
    k_final<<<dim3(5, 16, 4), 128>>>(fout, ctw, ctb, out);
}

// round 2
// speedup vs baseline: 1.2208x; 1.2208x over previous
#include <cuda_runtime.h>

// ---------------------------------------------------------------------------
// Problem constants
// ---------------------------------------------------------------------------
namespace {
constexpr int Bc   = 4;
constexpr int Cc   = 64;
constexpr int Hc   = 256;
constexpr int Wc   = 320;
constexpr int HWc  = Hc * Wc;        // 81920
constexpr int NPIX = Bc * HWc;       // 327680
constexpr int NB   = 320;            // pixel-blocks per conv group (10 x 32)
constexpr int OCG  = 14;             // output channels per conv group
constexpr int NG   = 6;              // groups -> 84 padded channels (83 used)
}

// ---------------------------------------------------------------------------
// Device scratch (static allocations only -- no cudaMalloc allowed)
// ---------------------------------------------------------------------------
__device__ float g_wall[84 * 576];      // packed conv weights [oc][ic][tap]
__device__ float g_bias[84];            // bias (ck only, else 0)
__device__ float g_sp[83];              // spatial gaussian tables (9+25+49)
__device__ float g_conv[83 * NPIX];     // raw conv outputs [oc][pix]
__device__ float g_psum[80 * NB];       // BN partial sums
__device__ float g_psq[80 * NB];        // BN partial sum-squares
__device__ float g_bnscale[80];
__device__ float g_bnshift[80];
__device__ float g_weights[83 * NPIX];  // normalized per-pixel kernels [k][pix]
__device__ float g_conf[3 * NPIX];
__device__ float g_hn[6 * NPIX];        // ping-pong hn3/5/7
__device__ float g_hns[3 * NPIX];       // hn, mid blend, final blend

// ---------------------------------------------------------------------------
// f32x2 packed-FMA helpers (sm_100+: fma.rn.f32x2 -> FFMA2, 2x fp32 rate)
// ---------------------------------------------------------------------------
__device__ __forceinline__ unsigned long long pk2(float lo, float hi) {
    unsigned long long r;
    asm("mov.b64 %0,{%1,%2};" : "=l"(r) : "f"(lo), "f"(hi));
    return r;
}
__device__ __forceinline__ unsigned long long splat2(float v) { return pk2(v, v); }
__device__ __forceinline__ void fma2(unsigned long long& d, unsigned long long a,
                                     unsigned long long b) {
    asm("fma.rn.f32x2 %0,%1,%2,%0;" : "+l"(d) : "l"(a), "l"(b));
}
__device__ __forceinline__ void unpk2(unsigned long long v, float& lo, float& hi) {
    asm("mov.b64 {%0,%1},%2;" : "=f"(lo), "=f"(hi) : "l"(v));
}

// ---------------------------------------------------------------------------
// K0a: pack all conv weights into one padded [84][64][9] tensor + bias
// ---------------------------------------------------------------------------
__global__ void k_pack(const float* __restrict__ w3, const float* __restrict__ w5,
                       const float* __restrict__ w7, const float* __restrict__ ckw,
                       const float* __restrict__ ckb) {
    int i0 = blockIdx.x * blockDim.x + threadIdx.x;
    for (int idx = i0; idx < 84 * 576; idx += gridDim.x * blockDim.x) {
        int oc = idx / 576, rest = idx % 576;
        float v = 0.f;
        if (oc < 8)        v = w3[oc * 576 + rest];
        else if (oc < 32)  v = w5[(oc - 8) * 576 + rest];
        else if (oc < 80)  v = w7[(oc - 32) * 576 + rest];
        else if (oc < 83)  v = ckw[(oc - 80) * 576 + rest];
        g_wall[idx] = v;
    }
    if (i0 < 84) g_bias[i0] = (i0 >= 80 && i0 < 83) ? ckb[i0 - 80] : 0.f;
}

// ---------------------------------------------------------------------------
// K0b: spatial gaussian tables from device-resident sigmas
// ---------------------------------------------------------------------------
__global__ void k_sp(const float* __restrict__ s3, const float* __restrict__ s5,
                     const float* __restrict__ s7) {
    int t = threadIdx.x;
    if (t >= 83) return;
    int d, k;
    float sig;
    if (t < 9)       { d = 3; k = t;      sig = *s3; }
    else if (t < 34) { d = 5; k = t - 9;  sig = *s5; }
    else             { d = 7; k = t - 34; sig = *s7; }
    int kh = k / d, kw = k % d;
    float x = -1.f + 2.f * (float)kh / (float)(d - 1);
    float y = -1.f + 2.f * (float)kw / (float)(d - 1);
    g_sp[t] = expf(-(x * x + y * y) / (2.f * sig * sig));
}

// ---------------------------------------------------------------------------
// K1: 83-channel 3x3 conv over fout.
//     Register-blocked: 32x32 pixel tile, 256 threads, 2x2 quad per thread.
//     Each weight LDS.64 is reused by 4 FFMA2 (28 independent accumulators).
//     grid (10, 32, 6): x = W tile, y = H tile(8) * batch(4), z = oc group
// ---------------------------------------------------------------------------
__global__ __launch_bounds__(256, 2) void k_conv(const float* __restrict__ fout) {
    __shared__ float  s_in[4][34][34];
    __shared__ float2 s_w[4][9][7];
    __shared__ float  s_rs[8][14];
    __shared__ float  s_rq[8][14];

    const int tid = threadIdx.x;
    const int qx = tid & 15;             // quad col 0..15
    const int qy = tid >> 4;             // quad row 0..15
    const int b  = blockIdx.y >> 3;
    const int y0 = (blockIdx.y & 7) * 32;
    const int x0 = blockIdx.x * 32;
    const int ocb = blockIdx.z * OCG;

    unsigned long long acc[2][2][7] = {};

    for (int icb = 0; icb < Cc; icb += 4) {
        __syncthreads();
        // weights: 4 ic x 9 taps x 14 oc = 504 floats
        for (int idx = tid; idx < 504; idx += 256) {
            int ic = idx / 126, rem = idx % 126;
            int t = rem / 14, j = rem % 14;
            ((float*)s_w)[idx] = g_wall[(ocb + j) * 576 + (icb + ic) * 9 + t];
        }
        // input tile: 4 ic x 34 x 34 (zero-padded halo)
        for (int idx = tid; idx < 4624; idx += 256) {
            int ic = idx / 1156, rem = idx % 1156;
            int r = rem / 34, c = rem % 34;
            int gh = y0 + r - 1, gw = x0 + c - 1;
            float v = 0.f;
            if ((unsigned)gh < (unsigned)Hc && (unsigned)gw < (unsigned)Wc)
                v = fout[((b * Cc + icb + ic) * Hc + gh) * Wc + gw];
            s_in[ic][r][c] = v;
        }
        __syncthreads();
#pragma unroll
        for (int ic = 0; ic < 4; ic++) {
            float x[4][4];
#pragma unroll
            for (int r = 0; r < 4; r++)
#pragma unroll
                for (int c = 0; c < 4; c++)
                    x[r][c] = s_in[ic][qy * 2 + r][qx * 2 + c];
#pragma unroll
            for (int t = 0; t < 9; t++) {
                const int th = t / 3, tw = t % 3;
                unsigned long long w2[7];
#pragma unroll
                for (int p = 0; p < 7; p++)
                    w2[p] = *(const unsigned long long*)&s_w[ic][t][p];
                unsigned long long v00 = splat2(x[th][tw]);
                unsigned long long v01 = splat2(x[th][tw + 1]);
                unsigned long long v10 = splat2(x[th + 1][tw]);
                unsigned long long v11 = splat2(x[th + 1][tw + 1]);
#pragma unroll
                for (int p = 0; p < 7; p++) {
                    fma2(acc[0][0][p], v00, w2[p]);
                    fma2(acc[0][1][p], v01, w2[p]);
                    fma2(acc[1][0][p], v10, w2[p]);
                    fma2(acc[1][1][p], v11, w2[p]);
                }
            }
        }
    }

    // unpack: fv[py][px][j]
    float fv[2][2][14];
#pragma unroll
    for (int py = 0; py < 2; py++)
#pragma unroll
        for (int px = 0; px < 2; px++)
#pragma unroll
            for (int p = 0; p < 7; p++)
                unpk2(acc[py][px][p], fv[py][px][2 * p], fv[py][px][2 * p + 1]);

    // bias (zero except oc 80..82) then store as float2 (coalesced)
    const int px0 = x0 + qx * 2;
    const int py0 = y0 + qy * 2;
#pragma unroll
    for (int j = 0; j < 14; j++) {
        int oc = ocb + j;
        if (oc < 83) {
            float bb = g_bias[oc];
#pragma unroll
            for (int py = 0; py < 2; py++) {
                float2 o2 = make_float2(fv[py][0][j] + bb, fv[py][1][j] + bb);
                *(float2*)&g_conv[oc * NPIX + b * HWc + (py0 + py) * Wc + px0] = o2;
            }
        }
    }

    // BN partial sums (bias is zero on BN channels, so fv is pre-bias there)
#pragma unroll
    for (int j = 0; j < 14; j++) {
        float s = fv[0][0][j] + fv[0][1][j] + fv[1][0][j] + fv[1][1][j];
        float q = fv[0][0][j] * fv[0][0][j] + fv[0][1][j] * fv[0][1][j] +
                  fv[1][0][j] * fv[1][0][j] + fv[1][1][j] * fv[1][1][j];
#pragma unroll
        for (int off = 16; off; off >>= 1) {
            s += __shfl_xor_sync(0xffffffffu, s, off);
            q += __shfl_xor_sync(0xffffffffu, q, off);
        }
        if ((tid & 31) == 0) { s_rs[tid >> 5][j] = s; s_rq[tid >> 5][j] = q; }
    }
    __syncthreads();
    if (tid < 14) {
        int oc = ocb + tid;
        if (oc < 80) {
            float S = 0.f, Q = 0.f;
#pragma unroll
            for (int w8 = 0; w8 < 8; w8++) { S += s_rs[w8][tid]; Q += s_rq[w8][tid]; }
            int pb = blockIdx.x + 10 * blockIdx.y;
            g_psum[oc * NB + pb] = S;
            g_psq[oc * NB + pb]  = Q;
        }
    }
}

// ---------------------------------------------------------------------------
// K2: finalize batchnorm statistics -> per-channel scale/shift
// ---------------------------------------------------------------------------
__global__ void k_bnstats(const float* __restrict__ g3, const float* __restrict__ b3,
                          const float* __restrict__ g5, const float* __restrict__ b5,
                          const float* __restrict__ g7, const float* __restrict__ b7) {
    __shared__ float sh[256], shq[256];
    int c = blockIdx.x;
    float S = 0.f, Q = 0.f;
    for (int i = threadIdx.x; i < NB; i += 256) {
        S += g_psum[c * NB + i];
        Q += g_psq[c * NB + i];
    }
    sh[threadIdx.x] = S; shq[threadIdx.x] = Q;
    __syncthreads();
    for (int s = 128; s; s >>= 1) {
        if (threadIdx.x < s) { sh[threadIdx.x] += sh[threadIdx.x + s]; shq[threadIdx.x] += shq[threadIdx.x + s]; }
        __syncthreads();
    }
    if (threadIdx.x == 0) {
        float mean = sh[0] / (float)NPIX;
        float var  = shq[0] / (float)NPIX - mean * mean;
        float gg, bb;
        if (c < 8)       { gg = g3[c];      bb = b3[c]; }
        else if (c < 32) { gg = g5[c - 8];  bb = b5[c - 8]; }
        else             { gg = g7[c - 32]; bb = b7[c - 32]; }
        float sc = gg / sqrtf(var + 1e-5f);
        g_bnscale[c] = sc;
        g_bnshift[c] = bb - mean * sc;
    }
}

// ---------------------------------------------------------------------------
// K3: per-pixel kernel generation + conf softmax + hn init
// ---------------------------------------------------------------------------
template <int N, int HF>
__device__ __forceinline__ void gen_group(int pix, int ocb, int spo) {
    float wv[N];
    float s = 0.f;
#pragma unroll
    for (int i = 0; i < N; i++) {
        float v = g_conv[(ocb + i) * NPIX + pix];
        v = fmaxf(fmaf(v, g_bnscale[ocb + i], g_bnshift[ocb + i]), 0.f);
        wv[i] = v;
        s += v;
    }
    float inv = 1.f / (s + 1e-6f);
    float mid = 1e-6f * inv;                // == 1 - s/(s+eps)
    float tot = mid * g_sp[spo + HF];
#pragma unroll
    for (int i = 0; i < N; i++) {
        int k = (i < HF) ? i : i + 1;
        tot += wv[i] * inv * g_sp[spo + k];
    }
    float sc = 1.f / fmaxf(tot, 1e-7f);
    g_weights[(spo + HF) * NPIX + pix] = mid * g_sp[spo + HF] * sc;
#pragma unroll
    for (int i = 0; i < N; i++) {
        int k = (i < HF) ? i : i + 1;
        g_weights[(spo + k) * NPIX + pix] = wv[i] * inv * g_sp[spo + k] * sc;
    }
}

__global__ __launch_bounds__(256) void k_wgen(const float* __restrict__ hn) {
    int pix = blockIdx.x * 256 + threadIdx.x;
    gen_group<8, 4>(pix, 0, 0);
    gen_group<24, 12>(pix, 8, 9);
    gen_group<48, 24>(pix, 32, 34);
    float c0 = g_conv[80 * NPIX + pix];
    float c1 = g_conv[81 * NPIX + pix];
    float c2 = g_conv[82 * NPIX + pix];
    float m = fmaxf(c0, fmaxf(c1, c2));
    float e0 = expf(c0 - m), e1 = expf(c1 - m), e2 = expf(c2 - m);
    float inv = 1.f / (e0 + e1 + e2);
    g_conf[pix]            = e0 * inv;
    g_conf[NPIX + pix]     = e1 * inv;
    g_conf[2 * NPIX + pix] = e2 * inv;
    float h = hn[pix];
    g_hn[pix] = h; g_hn[NPIX + pix] = h; g_hn[2 * NPIX + pix] = h;
    g_hns[pix] = h;
}

// ---------------------------------------------------------------------------
// K4: one propagation step for all three kernel sizes (ping-pong buffers)
// ---------------------------------------------------------------------------
template <int PK, int R, int SPO>
__device__ __forceinline__ float prop_one(int pix, int h, int w,
                                          const float* __restrict__ hsrc) {
    float o = 0.f;
#pragma unroll
    for (int kh = 0; kh < PK; kh++) {
        int hh = h + kh - R;
#pragma unroll
        for (int kw = 0; kw < PK; kw++) {
            int ww = w + kw - R;
            float x = 0.f;
            if ((unsigned)hh < (unsigned)Hc && (unsigned)ww < (unsigned)Wc)
                x = hsrc[pix + (kh - R) * Wc + (kw - R)];
            o = fmaf(g_weights[(SPO + kh * PK + kw) * NPIX + pix], x, o);
        }
    }
    return o;
}

__global__ __launch_bounds__(256) void k_prop(int srcBase, int dstBase, int blendIdx) {
    int pix = blockIdx.x * 256 + threadIdx.x;
    int rp = pix % HWc;
    int h = rp / Wc, w = rp % Wc;
    float o3 = prop_one<3, 1, 0>(pix, h, w, g_hn + (srcBase + 0) * NPIX);
    float o5 = prop_one<5, 2, 9>(pix, h, w, g_hn + (srcBase + 1) * NPIX);
    float o7 = prop_one<7, 3, 34>(pix, h, w, g_hn + (srcBase + 2) * NPIX);
    g_hn[(dstBase + 0) * NPIX + pix] = o3;
    g_hn[(dstBase + 1) * NPIX + pix] = o5;
    g_hn[(dstBase + 2) * NPIX + pix] = o7;
    if (blendIdx >= 0) {
        float r = g_conf[pix] * o3 + g_conf[NPIX + pix] * o5 + g_conf[2 * NPIX + pix] * o7;
        g_hns[blendIdx * NPIX + pix] = r;
    }
}

// ---------------------------------------------------------------------------
// K5: final 67->3 conv + softmax + weighted blend -> output
// ---------------------------------------------------------------------------
__global__ __launch_bounds__(128) void k_final(const float* __restrict__ fout,
                                               const float* __restrict__ ctw,
                                               const float* __restrict__ ctb,
                                               float* __restrict__ out) {
    __shared__ float s_t[2][18][66];
    __shared__ float s_wt[67][9][3];

    const int tid = threadIdx.x;
    const int sx = tid & 7, yy = tid >> 3;          // strip 0..7, row 0..15
    const int b = blockIdx.z;
    const int x0 = blockIdx.x * 64, y0 = blockIdx.y * 16;

    for (int idx = tid; idx < 67 * 27; idx += 128) {
        int o = idx % 3, t = (idx / 3) % 9, i = idx / 27;
        s_wt[i][t][o] = ctw[(o * 67 + i) * 9 + t];
    }

    unsigned long long acc[3][4] = {};

    for (int ic0 = 0; ic0 < 67; ic0 += 2) {
        int nic = (67 - ic0) < 2 ? (67 - ic0) : 2;
        __syncthreads();
        for (int idx = tid; idx < nic * 1188; idx += 128) {
            int icl = idx / 1188, rem = idx % 1188;
            int r = rem / 66, c = rem % 66;
            int gh = y0 + r - 1, gw = x0 + c - 1;
            float v = 0.f;
            if ((unsigned)gh < (unsigned)Hc && (unsigned)gw < (unsigned)Wc) {
                int ic = ic0 + icl;
                v = (ic < 64) ? fout[((b * Cc + ic) * Hc + gh) * Wc + gw]
                              : g_hns[(ic - 64) * NPIX + b * HWc + gh * Wc + gw];
            }
            s_t[icl][r][c] = v;
        }
        __syncthreads();
        for (int icl = 0; icl < nic; icl++) {
            const int ic = ic0 + icl;
            const int c0 = sx * 8;
            float r0[10], r1[10], r2[10];
#pragma unroll
            for (int c = 0; c < 10; c++) {
                r0[c] = s_t[icl][yy][c0 + c];
                r1[c] = s_t[icl][yy + 1][c0 + c];
                r2[c] = s_t[icl][yy + 2][c0 + c];
            }
            unsigned long long p0[9], p1[9], p2[9];
#pragma unroll
            for (int c = 0; c < 9; c++) {
                p0[c] = pk2(r0[c], r0[c + 1]);
                p1[c] = pk2(r1[c], r1[c + 1]);
                p2[c] = pk2(r2[c], r2[c + 1]);
            }
#pragma unroll
            for (int kh = 0; kh < 3; kh++) {
                const unsigned long long* pr = (kh == 0) ? p0 : (kh == 1) ? p1 : p2;
#pragma unroll
                for (int kw = 0; kw < 3; kw++) {
#pragma unroll
                    for (int o = 0; o < 3; o++) {
                        unsigned long long ws = splat2(s_wt[ic][kh * 3 + kw][o]);
#pragma unroll
                        for (int j = 0; j < 4; j++) fma2(acc[o][j], pr[kw + 2 * j], ws);
                    }
                }
            }
        }
    }

    float a[3][8];
#pragma unroll
    for (int o = 0; o < 3; o++)
#pragma unroll
        for (int j = 0; j < 4; j++) unpk2(acc[o][j], a[o][2 * j], a[o][2 * j + 1]);

    float bb0 = ctb[0], bb1 = ctb[1], bb2 = ctb[2];
    int basepix = b * HWc + (y0 + yy) * Wc + x0 + sx * 8;
#pragma unroll
    for (int e = 0; e < 8; e++) {
        float v0 = a[0][e] + bb0, v1 = a[1][e] + bb1, v2 = a[2][e] + bb2;
        float m = fmaxf(v0, fmaxf(v1, v2));
        float e0 = expf(v0 - m), e1 = expf(v1 - m), e2 = expf(v2 - m);
        float inv = 1.f / (e0 + e1 + e2);
        int pix = basepix + e;
        float h0v = g_hns[pix], h1v = g_hns[NPIX + pix], h2v = g_hns[2 * NPIX + pix];
        out[pix] = (e0 * h0v + e1 * h1v + e2 * h2v) * inv;
    }
}

// ---------------------------------------------------------------------------
// Launcher
// ---------------------------------------------------------------------------
extern "C" void kernel_launch(void* const* d_in, const int* in_sizes, int n_in,
                              void* d_out, int out_size) {
    const float* fout = (const float*)d_in[0];
    const float* hn   = (const float*)d_in[1];
    // d_in[2] = h0 (unused by reference)
    const float* w3c  = (const float*)d_in[3];
    const float* w3g  = (const float*)d_in[4];
    const float* w3b  = (const float*)d_in[5];
    const float* w5c  = (const float*)d_in[6];
    const float* w5g  = (const float*)d_in[7];
    const float* w5b  = (const float*)d_in[8];
    const float* w7c  = (const float*)d_in[9];
    const float* w7g  = (const float*)d_in[10];
    const float* w7b  = (const float*)d_in[11];
    const float* ckw  = (const float*)d_in[12];
    const float* ckb  = (const float*)d_in[13];
    const float* ctw  = (const float*)d_in[14];
    const float* ctb  = (const float*)d_in[15];
    const float* sig3 = (const float*)d_in[16];
    const float* sig5 = (const float*)d_in[17];
    const float* sig7 = (const float*)d_in[18];
    float* out = (float*)d_out;

    k_pack<<<64, 256>>>(w3c, w5c, w7c, ckw, ckb);
    k_sp<<<1, 128>>>(sig3, sig5, sig7);
    k_conv<<<dim3(10, 32, NG), 256>>>(fout);
    k_bnstats<<<80, 256>>>(w3g, w3b, w5g, w5b, w7g, w7b);
    k_wgen<<<NPIX / 256, 256>>>(hn);
    k_prop<<<NPIX / 256, 256>>>(0, 3, -1);
    k_prop<<<NPIX / 256, 256>>>(3, 0, -1);
    k_prop<<<NPIX / 256, 256>>>(0, 3, 1);   // i == PT/2-1 -> hns[1]
    k_prop<<<NPIX / 256, 256>>>(3, 0, -1);
    k_prop<<<NPIX / 256, 256>>>(0, 3, -1);
    k_prop<<<NPIX / 256, 256>>>(3, 0, 2);   // final -> hns[2]
    k_final<<<dim3(5, 16, 4), 128>>>(fout, ctw, ctb, out);
}

// round 3
// speedup vs baseline: 1.2412x; 1.0167x over previous
#include <cuda_runtime.h>

// ---------------------------------------------------------------------------
// Problem constants
// ---------------------------------------------------------------------------
namespace {
constexpr int Bc   = 4;
constexpr int Cc   = 64;
constexpr int Hc   = 256;
constexpr int Wc   = 320;
constexpr int HWc  = Hc * Wc;        // 81920
constexpr int NPIX = Bc * HWc;       // 327680
constexpr int NB   = 320;            // pixel-blocks per conv group (10 x 32)
constexpr int OCG  = 14;             // output channels per conv group
constexpr int NG   = 6;              // groups -> 84 padded channels (83 used)
}

// ---------------------------------------------------------------------------
// Device scratch (static allocations only -- no cudaMalloc allowed)
// ---------------------------------------------------------------------------
__device__ float g_wall[84 * 576];      // packed conv weights [oc][ic][tap]
__device__ float g_bias[84];            // bias (ck only, else 0)
__device__ float g_sp[83];              // spatial gaussian tables (9+25+49)
__device__ float g_conv[83 * NPIX];     // raw conv outputs [oc][pix]
__device__ float g_psum[80 * NB];       // BN partial sums
__device__ float g_psq[80 * NB];        // BN partial sum-squares
__device__ float g_bnscale[80];
__device__ float g_bnshift[80];
__device__ float g_weights[83 * NPIX];  // normalized per-pixel kernels [k][pix]
__device__ float g_conf[3 * NPIX];
__device__ float g_hn[6 * NPIX];        // ping-pong hn3/5/7
__device__ float g_hns[3 * NPIX];       // hn, mid blend, final blend

// ---------------------------------------------------------------------------
// f32x2 packed-FMA helpers (sm_100+: fma.rn.f32x2 -> FFMA2, 2x fp32 rate)
// ---------------------------------------------------------------------------
__device__ __forceinline__ unsigned long long pk2(float lo, float hi) {
    unsigned long long r;
    asm("mov.b64 %0,{%1,%2};" : "=l"(r) : "f"(lo), "f"(hi));
    return r;
}
__device__ __forceinline__ unsigned long long splat2(float v) { return pk2(v, v); }
__device__ __forceinline__ void fma2(unsigned long long& d, unsigned long long a,
                                     unsigned long long b) {
    asm("fma.rn.f32x2 %0,%1,%2,%0;" : "+l"(d) : "l"(a), "l"(b));
}
__device__ __forceinline__ void unpk2(unsigned long long v, float& lo, float& hi) {
    asm("mov.b64 {%0,%1},%2;" : "=f"(lo), "=f"(hi) : "l"(v));
}

// ---------------------------------------------------------------------------
// K0a: pack all conv weights into one padded [84][64][9] tensor + bias
// ---------------------------------------------------------------------------
__global__ void k_pack(const float* __restrict__ w3, const float* __restrict__ w5,
                       const float* __restrict__ w7, const float* __restrict__ ckw,
                       const float* __restrict__ ckb) {
    int i0 = blockIdx.x * blockDim.x + threadIdx.x;
    for (int idx = i0; idx < 84 * 576; idx += gridDim.x * blockDim.x) {
        int oc = idx / 576, rest = idx % 576;
        float v = 0.f;
        if (oc < 8)        v = w3[oc * 576 + rest];
        else if (oc < 32)  v = w5[(oc - 8) * 576 + rest];
        else if (oc < 80)  v = w7[(oc - 32) * 576 + rest];
        else if (oc < 83)  v = ckw[(oc - 80) * 576 + rest];
        g_wall[idx] = v;
    }
    if (i0 < 84) g_bias[i0] = (i0 >= 80 && i0 < 83) ? ckb[i0 - 80] : 0.f;
}

// ---------------------------------------------------------------------------
// K0b: spatial gaussian tables from device-resident sigmas
// ---------------------------------------------------------------------------
__global__ void k_sp(const float* __restrict__ s3, const float* __restrict__ s5,
                     const float* __restrict__ s7) {
    int t = threadIdx.x;
    if (t >= 83) return;
    int d, k;
    float sig;
    if (t < 9)       { d = 3; k = t;      sig = *s3; }
    else if (t < 34) { d = 5; k = t - 9;  sig = *s5; }
    else             { d = 7; k = t - 34; sig = *s7; }
    int kh = k / d, kw = k % d;
    float x = -1.f + 2.f * (float)kh / (float)(d - 1);
    float y = -1.f + 2.f * (float)kw / (float)(d - 1);
    g_sp[t] = expf(-(x * x + y * y) / (2.f * sig * sig));
}

// ---------------------------------------------------------------------------
// K1: 83-channel 3x3 conv over fout.
//     Register-blocked: 32x32 pixel tile, 256 threads, 2x2 quad per thread.
//     Each weight LDS.64 is reused by 4 FFMA2 (28 independent accumulators).
//     grid (10, 32, 6): x = W tile, y = H tile(8) * batch(4), z = oc group
// ---------------------------------------------------------------------------
__global__ __launch_bounds__(256, 2) void k_conv(const float* __restrict__ fout) {
    __shared__ float  s_in[4][34][34];
    __shared__ float2 s_w[4][9][7];
    __shared__ float  s_rs[8][14];
    __shared__ float  s_rq[8][14];

    const int tid = threadIdx.x;
    const int qx = tid & 15;             // quad col 0..15
    const int qy = tid >> 4;             // quad row 0..15
    const int b  = blockIdx.y >> 3;
    const int y0 = (blockIdx.y & 7) * 32;
    const int x0 = blockIdx.x * 32;
    const int ocb = blockIdx.z * OCG;

    unsigned long long acc[2][2][7] = {};

    for (int icb = 0; icb < Cc; icb += 4) {
        __syncthreads();
        // weights: 4 ic x 9 taps x 14 oc = 504 floats
        for (int idx = tid; idx < 504; idx += 256) {
            int ic = idx / 126, rem = idx % 126;
            int t = rem / 14, j = rem % 14;
            ((float*)s_w)[idx] = g_wall[(ocb + j) * 576 + (icb + ic) * 9 + t];
        }
        // input tile: 4 ic x 34 x 34 (zero-padded halo)
        for (int idx = tid; idx < 4624; idx += 256) {
            int ic = idx / 1156, rem = idx % 1156;
            int r = rem / 34, c = rem % 34;
            int gh = y0 + r - 1, gw = x0 + c - 1;
            float v = 0.f;
            if ((unsigned)gh < (unsigned)Hc && (unsigned)gw < (unsigned)Wc)
                v = fout[((b * Cc + icb + ic) * Hc + gh) * Wc + gw];
            s_in[ic][r][c] = v;
        }
        __syncthreads();
#pragma unroll
        for (int ic = 0; ic < 4; ic++) {
            float x[4][4];
#pragma unroll
            for (int r = 0; r < 4; r++)
#pragma unroll
                for (int c = 0; c < 4; c++)
                    x[r][c] = s_in[ic][qy * 2 + r][qx * 2 + c];
#pragma unroll
            for (int t = 0; t < 9; t++) {
                const int th = t / 3, tw = t % 3;
                unsigned long long w2[7];
#pragma unroll
                for (int p = 0; p < 7; p++)
                    w2[p] = *(const unsigned long long*)&s_w[ic][t][p];
                unsigned long long v00 = splat2(x[th][tw]);
                unsigned long long v01 = splat2(x[th][tw + 1]);
                unsigned long long v10 = splat2(x[th + 1][tw]);
                unsigned long long v11 = splat2(x[th + 1][tw + 1]);
#pragma unroll
                for (int p = 0; p < 7; p++) {
                    fma2(acc[0][0][p], v00, w2[p]);
                    fma2(acc[0][1][p], v01, w2[p]);
                    fma2(acc[1][0][p], v10, w2[p]);
                    fma2(acc[1][1][p], v11, w2[p]);
                }
            }
        }
    }

    // unpack: fv[py][px][j]
    float fv[2][2][14];
#pragma unroll
    for (int py = 0; py < 2; py++)
#pragma unroll
        for (int px = 0; px < 2; px++)
#pragma unroll
            for (int p = 0; p < 7; p++)
                unpk2(acc[py][px][p], fv[py][px][2 * p], fv[py][px][2 * p + 1]);

    // bias (zero except oc 80..82) then store as float2 (coalesced)
    const int px0 = x0 + qx * 2;
    const int py0 = y0 + qy * 2;
#pragma unroll
    for (int j = 0; j < 14; j++) {
        int oc = ocb + j;
        if (oc < 83) {
            float bb = g_bias[oc];
#pragma unroll
            for (int py = 0; py < 2; py++) {
                float2 o2 = make_float2(fv[py][0][j] + bb, fv[py][1][j] + bb);
                *(float2*)&g_conv[oc * NPIX + b * HWc + (py0 + py) * Wc + px0] = o2;
            }
        }
    }

    // BN partial sums (bias is zero on BN channels, so fv is pre-bias there)
#pragma unroll
    for (int j = 0; j < 14; j++) {
        float s = fv[0][0][j] + fv[0][1][j] + fv[1][0][j] + fv[1][1][j];
        float q = fv[0][0][j] * fv[0][0][j] + fv[0][1][j] * fv[0][1][j] +
                  fv[1][0][j] * fv[1][0][j] + fv[1][1][j] * fv[1][1][j];
#pragma unroll
        for (int off = 16; off; off >>= 1) {
            s += __shfl_xor_sync(0xffffffffu, s, off);
            q += __shfl_xor_sync(0xffffffffu, q, off);
        }
        if ((tid & 31) == 0) { s_rs[tid >> 5][j] = s; s_rq[tid >> 5][j] = q; }
    }
    __syncthreads();
    if (tid < 14) {
        int oc = ocb + tid;
        if (oc < 80) {
            float S = 0.f, Q = 0.f;
#pragma unroll
            for (int w8 = 0; w8 < 8; w8++) { S += s_rs[w8][tid]; Q += s_rq[w8][tid]; }
            int pb = blockIdx.x + 10 * blockIdx.y;
            g_psum[oc * NB + pb] = S;
            g_psq[oc * NB + pb]  = Q;
        }
    }
}

// ---------------------------------------------------------------------------
// K2: finalize batchnorm statistics -> per-channel scale/shift
// ---------------------------------------------------------------------------
__global__ void k_bnstats(const float* __restrict__ g3, const float* __restrict__ b3,
                          const float* __restrict__ g5, const float* __restrict__ b5,
                          const float* __restrict__ g7, const float* __restrict__ b7) {
    __shared__ float sh[256], shq[256];
    int c = blockIdx.x;
    float S = 0.f, Q = 0.f;
    for (int i = threadIdx.x; i < NB; i += 256) {
        S += g_psum[c * NB + i];
        Q += g_psq[c * NB + i];
    }
    sh[threadIdx.x] = S; shq[threadIdx.x] = Q;
    __syncthreads();
    for (int s = 128; s; s >>= 1) {
        if (threadIdx.x < s) { sh[threadIdx.x] += sh[threadIdx.x + s]; shq[threadIdx.x] += shq[threadIdx.x + s]; }
        __syncthreads();
    }
    if (threadIdx.x == 0) {
        float mean = sh[0] / (float)NPIX;
        float var  = shq[0] / (float)NPIX - mean * mean;
        float gg, bb;
        if (c < 8)       { gg = g3[c];      bb = b3[c]; }
        else if (c < 32) { gg = g5[c - 8];  bb = b5[c - 8]; }
        else             { gg = g7[c - 32]; bb = b7[c - 32]; }
        float sc = gg / sqrtf(var + 1e-5f);
        g_bnscale[c] = sc;
        g_bnshift[c] = bb - mean * sc;
    }
}

// ---------------------------------------------------------------------------
// K3: per-pixel kernel generation + conf softmax + hn init
// ---------------------------------------------------------------------------
template <int N, int HF>
__device__ __forceinline__ void gen_group(int pix, int ocb, int spo) {
    float wv[N];
    float s = 0.f;
#pragma unroll
    for (int i = 0; i < N; i++) {
        float v = g_conv[(ocb + i) * NPIX + pix];
        v = fmaxf(fmaf(v, g_bnscale[ocb + i], g_bnshift[ocb + i]), 0.f);
        wv[i] = v;
        s += v;
    }
    float inv = 1.f / (s + 1e-6f);
    float mid = 1e-6f * inv;                // == 1 - s/(s+eps)
    float tot = mid * g_sp[spo + HF];
#pragma unroll
    for (int i = 0; i < N; i++) {
        int k = (i < HF) ? i : i + 1;
        tot += wv[i] * inv * g_sp[spo + k];
    }
    float sc = 1.f / fmaxf(tot, 1e-7f);
    g_weights[(spo + HF) * NPIX + pix] = mid * g_sp[spo + HF] * sc;
#pragma unroll
    for (int i = 0; i < N; i++) {
        int k = (i < HF) ? i : i + 1;
        g_weights[(spo + k) * NPIX + pix] = wv[i] * inv * g_sp[spo + k] * sc;
    }
}

__global__ __launch_bounds__(256) void k_wgen(const float* __restrict__ hn) {
    int pix = blockIdx.x * 256 + threadIdx.x;
    gen_group<8, 4>(pix, 0, 0);
    gen_group<24, 12>(pix, 8, 9);
    gen_group<48, 24>(pix, 32, 34);
    float c0 = g_conv[80 * NPIX + pix];
    float c1 = g_conv[81 * NPIX + pix];
    float c2 = g_conv[82 * NPIX + pix];
    float m = fmaxf(c0, fmaxf(c1, c2));
    float e0 = expf(c0 - m), e1 = expf(c1 - m), e2 = expf(c2 - m);
    float inv = 1.f / (e0 + e1 + e2);
    g_conf[pix]            = e0 * inv;
    g_conf[NPIX + pix]     = e1 * inv;
    g_conf[2 * NPIX + pix] = e2 * inv;
    float h = hn[pix];
    g_hn[pix] = h; g_hn[NPIX + pix] = h; g_hn[2 * NPIX + pix] = h;
    g_hns[pix] = h;
}

// ---------------------------------------------------------------------------
// K4: one propagation step for all three kernel sizes (ping-pong buffers)
// ---------------------------------------------------------------------------
template <int PK, int R, int SPO>
__device__ __forceinline__ float prop_one(int pix, int h, int w,
                                          const float* __restrict__ hsrc) {
    float o = 0.f;
#pragma unroll
    for (int kh = 0; kh < PK; kh++) {
        int hh = h + kh - R;
#pragma unroll
        for (int kw = 0; kw < PK; kw++) {
            int ww = w + kw - R;
            float x = 0.f;
            if ((unsigned)hh < (unsigned)Hc && (unsigned)ww < (unsigned)Wc)
                x = hsrc[pix + (kh - R) * Wc + (kw - R)];
            o = fmaf(g_weights[(SPO + kh * PK + kw) * NPIX + pix], x, o);
        }
    }
    return o;
}

__global__ __launch_bounds__(256) void k_prop(int srcBase, int dstBase, int blendIdx) {
    int pix = blockIdx.x * 256 + threadIdx.x;
    int rp = pix % HWc;
    int h = rp / Wc, w = rp % Wc;
    float o3 = prop_one<3, 1, 0>(pix, h, w, g_hn + (srcBase + 0) * NPIX);
    float o5 = prop_one<5, 2, 9>(pix, h, w, g_hn + (srcBase + 1) * NPIX);
    float o7 = prop_one<7, 3, 34>(pix, h, w, g_hn + (srcBase + 2) * NPIX);
    g_hn[(dstBase + 0) * NPIX + pix] = o3;
    g_hn[(dstBase + 1) * NPIX + pix] = o5;
    g_hn[(dstBase + 2) * NPIX + pix] = o7;
    if (blendIdx >= 0) {
        float r = g_conf[pix] * o3 + g_conf[NPIX + pix] * o5 + g_conf[2 * NPIX + pix] * o7;
        g_hns[blendIdx * NPIX + pix] = r;
    }
}

// ---------------------------------------------------------------------------
// K5: final 67->3 conv + softmax + weighted blend -> output
// ---------------------------------------------------------------------------
__global__ __launch_bounds__(128) void k_final(const float* __restrict__ fout,
                                               const float* __restrict__ ctw,
                                               const float* __restrict__ ctb,
                                               float* __restrict__ out) {
    __shared__ float s_t[2][18][66];
    __shared__ float s_wt[67][9][3];

    const int tid = threadIdx.x;
    const int sx = tid & 7, yy = tid >> 3;          // strip 0..7, row 0..15
    const int b = blockIdx.z;
    const int x0 = blockIdx.x * 64, y0 = blockIdx.y * 16;

    for (int idx = tid; idx < 67 * 27; idx += 128) {
        int o = idx % 3, t = (idx / 3) % 9, i = idx / 27;
        s_wt[i][t][o] = ctw[(o * 67 + i) * 9 + t];
    }

    unsigned long long acc[3][4] = {};

    for (int ic0 = 0; ic0 < 67; ic0 += 2) {
        int nic = (67 - ic0) < 2 ? (67 - ic0) : 2;
        __syncthreads();
        for (int idx = tid; idx < nic * 1188; idx += 128) {
            int icl = idx / 1188, rem = idx % 1188;
            int r = rem / 66, c = rem % 66;
            int gh = y0 + r - 1, gw = x0 + c - 1;
            float v = 0.f;
            if ((unsigned)gh < (unsigned)Hc && (unsigned)gw < (unsigned)Wc) {
                int ic = ic0 + icl;
                v = (ic < 64) ? fout[((b * Cc + ic) * Hc + gh) * Wc + gw]
                              : g_hns[(ic - 64) * NPIX + b * HWc + gh * Wc + gw];
            }
            s_t[icl][r][c] = v;
        }
        __syncthreads();
        for (int icl = 0; icl < nic; icl++) {
            const int ic = ic0 + icl;
            const int c0 = sx * 8;
            float r0[10], r1[10], r2[10];
#pragma unroll
            for (int c = 0; c < 10; c++) {
                r0[c] = s_t[icl][yy][c0 + c];
                r1[c] = s_t[icl][yy + 1][c0 + c];
                r2[c] = s_t[icl][yy + 2][c0 + c];
            }
            unsigned long long p0[9], p1[9], p2[9];
#pragma unroll
            for (int c = 0; c < 9; c++) {
                p0[c] = pk2(r0[c], r0[c + 1]);
                p1[c] = pk2(r1[c], r1[c + 1]);
                p2[c] = pk2(r2[c], r2[c + 1]);
            }
#pragma unroll
            for (int kh = 0; kh < 3; kh++) {
                const unsigned long long* pr = (kh == 0) ? p0 : (kh == 1) ? p1 : p2;
#pragma unroll
                for (int kw = 0; kw < 3; kw++) {
#pragma unroll
                    for (int o = 0; o < 3; o++) {
                        unsigned long long ws = splat2(s_wt[ic][kh * 3 + kw][o]);
#pragma unroll
                        for (int j = 0; j < 4; j++) fma2(acc[o][j], pr[kw + 2 * j], ws);
                    }
                }
            }
        }
    }

    float a[3][8];
#pragma unroll
    for (int o = 0; o < 3; o++)
#pragma unroll
        for (int j = 0; j < 4; j++) unpk2(acc[o][j], a[o][2 * j], a[o][2 * j + 1]);

    float bb0 = ctb[0], bb1 = ctb[1], bb2 = ctb[2];
    int basepix = b * HWc + (y0 + yy) * Wc + x0 + sx * 8;
#pragma unroll
    for (int e = 0; e < 8; e++) {
        float v0 = a[0][e] + bb0, v1 = a[1][e] + bb1, v2 = a[2][e] + bb2;
        float m = fmaxf(v0, fmaxf(v1, v2));
        float e0 = expf(v0 - m), e1 = expf(v1 - m), e2 = expf(v2 - m);
        float inv = 1.f / (e0 + e1 + e2);
        int pix = basepix + e;
        float h0v = g_hns[pix], h1v = g_hns[NPIX + pix], h2v = g_hns[2 * NPIX + pix];
        out[pix] = (e0 * h0v + e1 * h1v + e2 * h2v) * inv;
    }
}

// ---------------------------------------------------------------------------
// Launcher
// ---------------------------------------------------------------------------
extern "C" void kernel_launch(void* const* d_in, const int* in_sizes, int n_in,
                              void* d_out, int out_size) {
    const float* fout = (const float*)d_in[0];
    const float* hn   = (const float*)d_in[1];
    // d_in[2] = h0 (unused by reference)
    const float* w3c  = (const float*)d_in[3];
    const float* w3g  = (const float*)d_in[4];
    const float* w3b  = (const float*)d_in[5];
    const float* w5c  = (const float*)d_in[6];
    const float* w5g  = (const float*)d_in[7];
    const float* w5b  = (const float*)d_in[8];
    const float* w7c  = (const float*)d_in[9];
    const float* w7g  = (const float*)d_in[10];
    const float* w7b  = (const float*)d_in[11];
    const float* ckw  = (const float*)d_in[12];
    const float* ckb  = (const float*)d_in[13];
    const float* ctw  = (const float*)d_in[14];
    const float* ctb  = (const float*)d_in[15];
    const float* sig3 = (const float*)d_in[16];
    const float* sig5 = (const float*)d_in[17];
    const float* sig7 = (const float*)d_in[18];
    float* out = (float*)d_out;

    k_pack<<<64, 256>>>(w3c, w5c, w7c, ckw, ckb);
    k_sp<<<1, 128>>>(sig3, sig5, sig7);
    k_conv<<<dim3(10, 32, NG), 256>>>(fout);
    k_bnstats<<<80, 256>>>(w3g, w3b, w5g, w5b, w7g, w7b);
    k_wgen<<<NPIX / 256, 256>>>(hn);
    k_prop<<<NPIX / 256, 256>>>(0, 3, -1);
    k_prop<<<NPIX / 256, 256>>>(3, 0, -1);
    k_prop<<<NPIX / 256, 256>>>(0, 3, 1);   // i == PT/2-1 -> hns[1]
    k_prop<<<NPIX / 256, 256>>>(3, 0, -1);
    k_prop<<<NPIX / 256, 256>>>(0, 3, -1);
    k_prop<<<NPIX / 256, 256>>>(3, 0, 2);   // final -> hns[2]
    k_final<<<dim3(5, 16, 4), 128>>>(fout, ctw, ctb, out);
}